// round 15
// baseline (speedup 1.0000x reference)
#include <cuda_runtime.h>
#include <cuda_bf16.h>
#include <cstdint>

// Problem constants
#define BB     4
#define S_LEN  2048
#define T_LEN  2048
#define HDIM   1024
#define ADIM   1024
#define NHEAD  16
#define HEADD  64
#define MROWS  8192   // B*S == B*T

// ---------------------------------------------------------------------------
// Device scratch — zero-initialized; K/V compacted tails stay 0 (deterministic)
// ---------------------------------------------------------------------------
__device__ __align__(16) __nv_bfloat16 g_xh[MROWS * HDIM];
__device__ __align__(16) __nv_bfloat16 g_xl[MROWS * HDIM];
__device__ __align__(16) __nv_bfloat16 g_yh[MROWS * HDIM];
__device__ __align__(16) __nv_bfloat16 g_yl[MROWS * HDIM];
__device__ __align__(16) __nv_bfloat16 g_qh[MROWS * ADIM];
__device__ __align__(16) __nv_bfloat16 g_ql[MROWS * ADIM];
__device__ __align__(16) __nv_bfloat16 g_kh[MROWS * ADIM];
__device__ __align__(16) __nv_bfloat16 g_kl[MROWS * ADIM];
__device__ __align__(16) __nv_bfloat16 g_vh[MROWS * ADIM];
__device__ __align__(16) __nv_bfloat16 g_vl[MROWS * ADIM];
__device__ __align__(16) __nv_bfloat16 g_oh[MROWS * ADIM];
__device__ __align__(16) __nv_bfloat16 g_ol[MROWS * ADIM];
__device__ __align__(16) __nv_bfloat16 g_wqh[ADIM * HDIM];
__device__ __align__(16) __nv_bfloat16 g_wql[ADIM * HDIM];
__device__ __align__(16) __nv_bfloat16 g_wkh[ADIM * HDIM];
__device__ __align__(16) __nv_bfloat16 g_wkl[ADIM * HDIM];
__device__ __align__(16) __nv_bfloat16 g_wvh[ADIM * HDIM];
__device__ __align__(16) __nv_bfloat16 g_wvl[ADIM * HDIM];
__device__ __align__(16) __nv_bfloat16 g_woh[HDIM * ADIM];
__device__ __align__(16) __nv_bfloat16 g_wol[HDIM * ADIM];
__device__ int g_dest[MROWS];   // compacted position per (b,t), -1 if masked
__device__ int g_cnt[BB];       // unmasked count per batch

// ---------------------------------------------------------------------------
// PTX helpers (sm_80-era: legal on plain sm_103 target)
// ---------------------------------------------------------------------------
__device__ __forceinline__ uint32_t smem_u32(const void* p) {
    uint32_t a;
    asm("{ .reg .u64 t; cvta.to.shared.u64 t, %1; cvt.u32.u64 %0, t; }" : "=r"(a) : "l"(p));
    return a;
}

#define CP_ASYNC16(smem, gptr) \
    asm volatile("cp.async.cg.shared.global [%0], [%1], 16;" \
                 :: "r"((uint32_t)(smem)), "l"(gptr) : "memory")
#define CP_ASYNC_COMMIT() asm volatile("cp.async.commit_group;" ::: "memory")
#define CP_ASYNC_WAIT0()  asm volatile("cp.async.wait_group 0;" ::: "memory")
#define CP_ASYNC_WAIT1()  asm volatile("cp.async.wait_group 1;" ::: "memory")

#define LDSM_X4(r0, r1, r2, r3, a) \
    asm volatile("ldmatrix.sync.aligned.m8n8.x4.shared.b16 {%0,%1,%2,%3}, [%4];" \
                 : "=r"(r0), "=r"(r1), "=r"(r2), "=r"(r3) : "r"(a))
#define LDSM_X4_T(r0, r1, r2, r3, a) \
    asm volatile("ldmatrix.sync.aligned.m8n8.x4.trans.shared.b16 {%0,%1,%2,%3}, [%4];" \
                 : "=r"(r0), "=r"(r1), "=r"(r2), "=r"(r3) : "r"(a))
#define LDSM_X2(r0, r1, a) \
    asm volatile("ldmatrix.sync.aligned.m8n8.x2.shared.b16 {%0,%1}, [%2];" \
                 : "=r"(r0), "=r"(r1) : "r"(a))

#define MMA_BF16(d, a, b) \
    asm volatile("mma.sync.aligned.m16n8k16.row.col.f32.bf16.bf16.f32 " \
                 "{%0,%1,%2,%3}, {%4,%5,%6,%7}, {%8,%9}, {%0,%1,%2,%3};" \
                 : "+f"((d)[0]), "+f"((d)[1]), "+f"((d)[2]), "+f"((d)[3]) \
                 : "r"((a)[0]), "r"((a)[1]), "r"((a)[2]), "r"((a)[3]), \
                   "r"((b)[0]), "r"((b)[1]))

// ---------------------------------------------------------------------------
// Mask prefix scan: dest[b*T+t] = compacted idx (or -1); cnt[b] = #unmasked
// ---------------------------------------------------------------------------
__global__ __launch_bounds__(256) void build_index_kernel(
    const int* __restrict__ mask, int* __restrict__ dest, int* __restrict__ cnts)
{
    __shared__ int warp_sums[8];
    const int b = blockIdx.x;
    const int* mb = mask + (size_t)b * T_LEN;
    const int tid = threadIdx.x;
    const int lane = tid & 31, wid = tid >> 5;

    int vals[8], local = 0;
#pragma unroll
    for (int i = 0; i < 8; i++) { vals[i] = (mb[tid * 8 + i] != 0) ? 1 : 0; local += vals[i]; }

    int pre = local;
#pragma unroll
    for (int o = 1; o < 32; o <<= 1) {
        int v = __shfl_up_sync(0xffffffffu, pre, o);
        if (lane >= o) pre += v;
    }
    if (lane == 31) warp_sums[wid] = pre;
    __syncthreads();
    int woff = 0;
#pragma unroll
    for (int i = 0; i < 8; i++) if (i < wid) woff += warp_sums[i];

    int excl = woff + pre - local;
#pragma unroll
    for (int i = 0; i < 8; i++) {
        dest[b * T_LEN + tid * 8 + i] = vals[i] ? excl : -1;
        excl += vals[i];
    }
    if (tid == 255) cnts[b] = woff + pre;
}

// ---------------------------------------------------------------------------
// Fused split (x and y via blockIdx.y)
// ---------------------------------------------------------------------------
__global__ __launch_bounds__(256) void split2_kernel(
    const float4* __restrict__ in0, uint2* __restrict__ h0p, uint2* __restrict__ l0p,
    const float4* __restrict__ in1, uint2* __restrict__ h1p, uint2* __restrict__ l1p,
    int n4)
{
    int i = blockIdx.x * 256 + threadIdx.x;
    if (i >= n4) return;
    const float4* in = blockIdx.y ? in1 : in0;
    uint2* hi = blockIdx.y ? h1p : h0p;
    uint2* lo = blockIdx.y ? l1p : l0p;
    float4 v = in[i];
    __nv_bfloat16 h0 = __float2bfloat16(v.x), h1 = __float2bfloat16(v.y);
    __nv_bfloat16 h2 = __float2bfloat16(v.z), h3 = __float2bfloat16(v.w);
    __nv_bfloat16 l0 = __float2bfloat16(v.x - __bfloat162float(h0));
    __nv_bfloat16 l1 = __float2bfloat16(v.y - __bfloat162float(h1));
    __nv_bfloat16 l2 = __float2bfloat16(v.z - __bfloat162float(h2));
    __nv_bfloat16 l3 = __float2bfloat16(v.w - __bfloat162float(h3));
    uint2 hw, lw;
    hw.x = (uint32_t)__bfloat16_as_ushort(h0) | ((uint32_t)__bfloat16_as_ushort(h1) << 16);
    hw.y = (uint32_t)__bfloat16_as_ushort(h2) | ((uint32_t)__bfloat16_as_ushort(h3) << 16);
    lw.x = (uint32_t)__bfloat16_as_ushort(l0) | ((uint32_t)__bfloat16_as_ushort(l1) << 16);
    lw.y = (uint32_t)__bfloat16_as_ushort(l2) | ((uint32_t)__bfloat16_as_ushort(l3) << 16);
    hi[i] = hw;
    lo[i] = lw;
}

// ---------------------------------------------------------------------------
// Fused transpose+split of all 4 weights (blockIdx.z selects)
// ---------------------------------------------------------------------------
__global__ __launch_bounds__(256) void transpose_split4_kernel(
    const float* __restrict__ w0, __nv_bfloat16* __restrict__ t0h, __nv_bfloat16* __restrict__ t0l,
    const float* __restrict__ w1, __nv_bfloat16* __restrict__ t1h, __nv_bfloat16* __restrict__ t1l,
    const float* __restrict__ w2, __nv_bfloat16* __restrict__ t2h, __nv_bfloat16* __restrict__ t2l,
    const float* __restrict__ w3, __nv_bfloat16* __restrict__ t3h, __nv_bfloat16* __restrict__ t3l)
{
    __shared__ float t[32][33];
    const float* W;
    __nv_bfloat16 *th, *tl;
    switch (blockIdx.z) {
        case 0: W = w0; th = t0h; tl = t0l; break;
        case 1: W = w1; th = t1h; tl = t1l; break;
        case 2: W = w2; th = t2h; tl = t2l; break;
        default: W = w3; th = t3h; tl = t3l; break;
    }
    int tx = threadIdx.x, ty = threadIdx.y;
    int n0 = blockIdx.x * 32, k0 = blockIdx.y * 32;
#pragma unroll
    for (int i = 0; i < 32; i += 8)
        t[ty + i][tx] = W[(size_t)(k0 + ty + i) * 1024 + n0 + tx];
    __syncthreads();
#pragma unroll
    for (int i = 0; i < 32; i += 8) {
        float v = t[tx][ty + i];
        __nv_bfloat16 h = __float2bfloat16(v);
        __nv_bfloat16 l = __float2bfloat16(v - __bfloat162float(h));
        size_t o = (size_t)(n0 + ty + i) * 1024 + k0 + tx;
        th[o] = h;
        tl[o] = l;
    }
}

// ---------------------------------------------------------------------------
// GEMM: CTA 128x64, 512 threads, 16 warps (4m x 4n), warp tile 32x16.
// acc = 16 regs -> fits 64-reg cap -> 2 CTAs x 512 = 32 warps/SM (full occ).
// 2 smem stages; B fragments via single ldmatrix.x4 per (ks, hi/lo).
// ---------------------------------------------------------------------------
#define G_K     1024
#define G_N     1024
#define BKC     32
#define PAD_B   80
#define A_MATB  (128 * PAD_B)
#define B_MATB  (64 * PAD_B)
#define OFF_AH  0
#define OFF_AL  (A_MATB)
#define OFF_BH  (2 * A_MATB)
#define OFF_BL  (2 * A_MATB + B_MATB)
#define STAGE_B (2 * A_MATB + 2 * B_MATB)   // 30720
#define GEMM_DSMEM (2 * STAGE_B)            // 61440

__device__ __forceinline__ void gemm_load_stage(
    uint32_t sb, const __nv_bfloat16* __restrict__ Ah, const __nv_bfloat16* __restrict__ Al,
    const __nv_bfloat16* __restrict__ Bh, const __nv_bfloat16* __restrict__ Bl,
    int m0, int n0, int k0, int tid)
{
    // A: 128 rows x 4 sg = 512 chunks; one per thread (hi + lo)
    {
        int r = tid >> 2, sg = tid & 3;
        uint32_t so = (uint32_t)(r * PAD_B + sg * 16);
        size_t ga = (size_t)(m0 + r) * G_K + k0 + sg * 8;
        CP_ASYNC16(sb + OFF_AH + so, Ah + ga);
        CP_ASYNC16(sb + OFF_AL + so, Al + ga);
    }
    // B: 64 rows x 4 sg = 256 chunks; first 256 threads (hi + lo)
    if (tid < 256) {
        int r = tid >> 2, sg = tid & 3;
        uint32_t so = (uint32_t)(r * PAD_B + sg * 16);
        size_t gb = (size_t)(n0 + r) * G_K + k0 + sg * 8;
        CP_ASYNC16(sb + OFF_BH + so, Bh + gb);
        CP_ASYNC16(sb + OFF_BL + so, Bl + gb);
    }
}

// Mainloop: accumulates split-bf16 product into acc[2][2][4]  (mf x nf x 4)
__device__ __forceinline__ void gemm_mainloop(
    uint32_t sm0, const __nv_bfloat16* __restrict__ Ah, const __nv_bfloat16* __restrict__ Al,
    const __nv_bfloat16* __restrict__ Bh, const __nv_bfloat16* __restrict__ Bl,
    int m0, int n0, int tid, int wm, int wn, int lane, float acc[2][2][4])
{
    const int t4 = lane >> 3;
    const uint32_t a_lane_off = (uint32_t)(((lane & 7) + ((t4 & 1) << 3)) * PAD_B
                                           + ((t4 >> 1) << 3) * 2);
    // B x4 lane mapping: g4=lane>>3: 0->nf0 klo, 1->nf0 khi, 2->nf1 klo, 3->nf1 khi
    const uint32_t b4_lane_off = (uint32_t)(((lane & 7) + ((lane >> 4) << 3)) * PAD_B
                                            + (((lane >> 3) & 1) << 4));

    gemm_load_stage(sm0, Ah, Al, Bh, Bl, m0, n0, 0, tid);
    CP_ASYNC_COMMIT();

    const int NCH = G_K / BKC;
    for (int kc = 0; kc < NCH; kc++) {
        const uint32_t sb = sm0 + (kc & 1) * STAGE_B;
        if (kc + 1 < NCH) {
            gemm_load_stage(sm0 + ((kc + 1) & 1) * STAGE_B, Ah, Al, Bh, Bl,
                            m0, n0, (kc + 1) * BKC, tid);
            CP_ASYNC_COMMIT();
            CP_ASYNC_WAIT1();
        } else {
            CP_ASYNC_WAIT0();
        }
        __syncthreads();

#pragma unroll
        for (int ks = 0; ks < 2; ks++) {
            const uint32_t kb = (uint32_t)(ks * 16 * 2);
            uint32_t bh[2][2], bl[2][2];
            {
                uint32_t base = (uint32_t)((wn * 16) * PAD_B) + kb + b4_lane_off;
                LDSM_X4(bh[0][0], bh[0][1], bh[1][0], bh[1][1], sb + OFF_BH + base);
                LDSM_X4(bl[0][0], bl[0][1], bl[1][0], bl[1][1], sb + OFF_BL + base);
            }
#pragma unroll
            for (int mf = 0; mf < 2; mf++) {
                uint32_t base = (uint32_t)((wm * 32 + mf * 16) * PAD_B) + kb + a_lane_off;
                uint32_t ah[4], al[4];
                LDSM_X4(ah[0], ah[1], ah[2], ah[3], sb + OFF_AH + base);
                LDSM_X4(al[0], al[1], al[2], al[3], sb + OFF_AL + base);
#pragma unroll
                for (int nf = 0; nf < 2; nf++) {
                    MMA_BF16(acc[mf][nf], ah, bh[nf]);
                    MMA_BF16(acc[mf][nf], ah, bl[nf]);
                    MMA_BF16(acc[mf][nf], al, bh[nf]);
                }
            }
        }
        __syncthreads();
    }
}

// Fused Q/K/V projections: blockIdx.z selects (A, W, bias, output, mode).
__global__ __launch_bounds__(512, 2) void gemm_qkv_kernel(
    const __nv_bfloat16* __restrict__ xh, const __nv_bfloat16* __restrict__ xl,
    const __nv_bfloat16* __restrict__ yh, const __nv_bfloat16* __restrict__ yl,
    const __nv_bfloat16* __restrict__ wqh, const __nv_bfloat16* __restrict__ wql,
    const __nv_bfloat16* __restrict__ wkh, const __nv_bfloat16* __restrict__ wkl,
    const __nv_bfloat16* __restrict__ wvh, const __nv_bfloat16* __restrict__ wvl,
    const float* __restrict__ bq, const float* __restrict__ bk, const float* __restrict__ bv,
    __nv_bfloat16* __restrict__ qh, __nv_bfloat16* __restrict__ ql,
    __nv_bfloat16* __restrict__ kh, __nv_bfloat16* __restrict__ kl,
    __nv_bfloat16* __restrict__ vh, __nv_bfloat16* __restrict__ vl,
    const int* __restrict__ dest)
{
    extern __shared__ __align__(16) char dsm[];
    const uint32_t sm0 = smem_u32(dsm);
    const int tid = threadIdx.x;
    const int wid = tid >> 5;
    const int lane = tid & 31;
    const int wm = wid >> 2;          // 0..3
    const int wn = wid & 3;           // 0..3
    const int m0 = blockIdx.y * 128;
    const int n0 = blockIdx.x * 64;
    const int z = blockIdx.z;

    const __nv_bfloat16* Ah = (z == 0) ? xh : yh;
    const __nv_bfloat16* Al = (z == 0) ? xl : yl;
    const __nv_bfloat16* Bh = (z == 0) ? wqh : ((z == 1) ? wkh : wvh);
    const __nv_bfloat16* Bl = (z == 0) ? wql : ((z == 1) ? wkl : wvl);
    const float* bias = (z == 0) ? bq : ((z == 1) ? bk : bv);
    __nv_bfloat16* Ch = (z == 0) ? qh : ((z == 1) ? kh : vh);
    __nv_bfloat16* Cl = (z == 0) ? ql : ((z == 1) ? kl : vl);
    const float scale = (z == 0) ? 0.125f : 1.0f;

    float acc[2][2][4];
#pragma unroll
    for (int i = 0; i < 2; i++)
#pragma unroll
        for (int j = 0; j < 2; j++)
#pragma unroll
            for (int c = 0; c < 4; c++) acc[i][j][c] = 0.0f;

    gemm_mainloop(sm0, Ah, Al, Bh, Bl, m0, n0, tid, wm, wn, lane, acc);

#pragma unroll
    for (int mf = 0; mf < 2; mf++) {
        int row0 = m0 + wm * 32 + mf * 16 + (lane >> 2);
        int row1 = row0 + 8;
        long cr0 = row0, cr1 = row1;
        bool wr0 = true, wr1 = true;
        if (z != 0) {
            int d0 = dest[row0], d1 = dest[row1];
            wr0 = d0 >= 0; wr1 = d1 >= 0;
            cr0 = (long)(row0 & ~(T_LEN - 1)) + d0;
            cr1 = (long)(row1 & ~(T_LEN - 1)) + d1;
        }
#pragma unroll
        for (int nf = 0; nf < 2; nf++) {
            int col = n0 + wn * 16 + nf * 8 + ((lane & 3) << 1);
            float b0 = bias[col], b1 = bias[col + 1];
            float o0 = scale * (acc[mf][nf][0] + b0);
            float o1 = scale * (acc[mf][nf][1] + b1);
            float o2 = scale * (acc[mf][nf][2] + b0);
            float o3 = scale * (acc[mf][nf][3] + b1);
            __nv_bfloat162 h0 = __float22bfloat162_rn(make_float2(o0, o1));
            float2 hf0 = __bfloat1622float2(h0);
            __nv_bfloat162 l0 = __float22bfloat162_rn(make_float2(o0 - hf0.x, o1 - hf0.y));
            __nv_bfloat162 h1 = __float22bfloat162_rn(make_float2(o2, o3));
            float2 hf1 = __bfloat1622float2(h1);
            __nv_bfloat162 l1 = __float22bfloat162_rn(make_float2(o2 - hf1.x, o3 - hf1.y));
            if (wr0) {
                *(__nv_bfloat162*)(Ch + (size_t)cr0 * G_N + col) = h0;
                *(__nv_bfloat162*)(Cl + (size_t)cr0 * G_N + col) = l0;
            }
            if (wr1) {
                *(__nv_bfloat162*)(Ch + (size_t)cr1 * G_N + col) = h1;
                *(__nv_bfloat162*)(Cl + (size_t)cr1 * G_N + col) = l1;
            }
        }
    }
}

// Output projection: fp32 epilogue.
__global__ __launch_bounds__(512, 2) void gemm_out_kernel(
    const __nv_bfloat16* __restrict__ Ah, const __nv_bfloat16* __restrict__ Al,
    const __nv_bfloat16* __restrict__ Bh, const __nv_bfloat16* __restrict__ Bl,
    const float* __restrict__ bias, float* __restrict__ Cf)
{
    extern __shared__ __align__(16) char dsm[];
    const uint32_t sm0 = smem_u32(dsm);
    const int tid = threadIdx.x;
    const int wid = tid >> 5;
    const int lane = tid & 31;
    const int wm = wid >> 2;
    const int wn = wid & 3;
    const int m0 = blockIdx.y * 128;
    const int n0 = blockIdx.x * 64;

    float acc[2][2][4];
#pragma unroll
    for (int i = 0; i < 2; i++)
#pragma unroll
        for (int j = 0; j < 2; j++)
#pragma unroll
            for (int c = 0; c < 4; c++) acc[i][j][c] = 0.0f;

    gemm_mainloop(sm0, Ah, Al, Bh, Bl, m0, n0, tid, wm, wn, lane, acc);

#pragma unroll
    for (int mf = 0; mf < 2; mf++) {
        int row0 = m0 + wm * 32 + mf * 16 + (lane >> 2);
        int row1 = row0 + 8;
#pragma unroll
        for (int nf = 0; nf < 2; nf++) {
            int col = n0 + wn * 16 + nf * 8 + ((lane & 3) << 1);
            float b0 = bias[col], b1 = bias[col + 1];
            float2 v0 = make_float2(acc[mf][nf][0] + b0, acc[mf][nf][1] + b1);
            float2 v1 = make_float2(acc[mf][nf][2] + b0, acc[mf][nf][3] + b1);
            *(float2*)(Cf + (size_t)row0 * G_N + col) = v0;
            *(float2*)(Cf + (size_t)row1 * G_N + col) = v1;
        }
    }
}

// ---------------------------------------------------------------------------
// Tensorized flash attention v3: K/V pre-compacted (unchanged from R13 win).
// ---------------------------------------------------------------------------
#define AT_ROWB 144
#define AT_MATB (64 * AT_ROWB)
#define AT_STGB (4 * AT_MATB)
#define AT_QB   (2 * 128 * AT_ROWB)
#define AT_KV0  AT_QB
#define AT_DSMEM (AT_QB + 2 * AT_STGB)  // 110592

__device__ __forceinline__ void at_load_kv(
    uint32_t sb, const __nv_bfloat16* khb, const __nv_bfloat16* klb,
    const __nv_bfloat16* vhb, const __nv_bfloat16* vlb, int t0, int tid)
{
#pragma unroll
    for (int it = 0; it < 2; it++) {
        int id = tid + it * 256;
        int r = id >> 3, c = id & 7;
        uint32_t so = (uint32_t)(r * AT_ROWB + c * 16);
        size_t go = (size_t)(t0 + r) * ADIM + c * 8;
        CP_ASYNC16(sb + 0 * AT_MATB + so, khb + go);
        CP_ASYNC16(sb + 1 * AT_MATB + so, klb + go);
        CP_ASYNC16(sb + 2 * AT_MATB + so, vhb + go);
        CP_ASYNC16(sb + 3 * AT_MATB + so, vlb + go);
    }
}

__global__ __launch_bounds__(256, 2) void flash_mma_kernel(
    const __nv_bfloat16* __restrict__ qh, const __nv_bfloat16* __restrict__ ql,
    const __nv_bfloat16* __restrict__ kh, const __nv_bfloat16* __restrict__ kl,
    const __nv_bfloat16* __restrict__ vh, const __nv_bfloat16* __restrict__ vl,
    const int* __restrict__ cnts,
    __nv_bfloat16* __restrict__ oh, __nv_bfloat16* __restrict__ ol)
{
    extern __shared__ __align__(16) char dsm[];
    const uint32_t sm0 = smem_u32(dsm);
    const int tid = threadIdx.x;
    const int w = tid >> 5;
    const int lane = tid & 31;
    const int s0 = blockIdx.x * 128;
    const int h = blockIdx.y;
    const int b = blockIdx.z;

    const int cnt = cnts[b];
    const int NTe = (cnt + 63) >> 6;

    const __nv_bfloat16* qhb = qh + (size_t)(b * S_LEN + s0) * ADIM + h * HEADD;
    const __nv_bfloat16* qlb = ql + (size_t)(b * S_LEN + s0) * ADIM + h * HEADD;
    const __nv_bfloat16* khb = kh + (size_t)(b * T_LEN) * ADIM + h * HEADD;
    const __nv_bfloat16* klb = kl + (size_t)(b * T_LEN) * ADIM + h * HEADD;
    const __nv_bfloat16* vhb = vh + (size_t)(b * T_LEN) * ADIM + h * HEADD;
    const __nv_bfloat16* vlb = vl + (size_t)(b * T_LEN) * ADIM + h * HEADD;

#pragma unroll
    for (int it = 0; it < 4; it++) {
        int id = tid + it * 256;
        int r = id >> 3, c = id & 7;
        uint32_t so = (uint32_t)(r * AT_ROWB + c * 16);
        size_t go = (size_t)r * ADIM + c * 8;
        CP_ASYNC16(sm0 + so, qhb + go);
        CP_ASYNC16(sm0 + 128 * AT_ROWB + so, qlb + go);
    }
    at_load_kv(sm0 + AT_KV0, khb, klb, vhb, vlb, 0, tid);
    CP_ASYNC_COMMIT();

    const int r8 = lane & 7;
    const int g = lane >> 3;
    const uint32_t q_base = sm0 + (uint32_t)((w * 16 + r8 + (g & 1) * 8) * AT_ROWB
                                             + ((g >> 1) << 3) * 2);

    float oacc[8][4];
#pragma unroll
    for (int i = 0; i < 8; i++)
#pragma unroll
        for (int c = 0; c < 4; c++) oacc[i][c] = 0.0f;
    float mr0 = -1e30f, mr1 = -1e30f, lr0 = 0.0f, lr1 = 0.0f;

    const int c2 = (lane & 3) << 1;

    CP_ASYNC_WAIT0();
    __syncthreads();

    for (int tc = 0; tc < NTe; tc++) {
        const uint32_t sb = sm0 + AT_KV0 + (tc & 1) * AT_STGB;
        if (tc + 1 < NTe) {
            at_load_kv(sm0 + AT_KV0 + ((tc + 1) & 1) * AT_STGB, khb, klb, vhb, vlb,
                       (tc + 1) * 64, tid);
            CP_ASYNC_COMMIT();
        }

        float s[8][4];
#pragma unroll
        for (int i = 0; i < 8; i++)
#pragma unroll
            for (int c = 0; c < 4; c++) s[i][c] = 0.0f;

#pragma unroll
        for (int kf = 0; kf < 4; kf++) {
            uint32_t qa = q_base + (uint32_t)(16 * kf * 2);
            uint32_t qfh[4], qfl[4];
            LDSM_X4(qfh[0], qfh[1], qfh[2], qfh[3], qa);
            LDSM_X4(qfl[0], qfl[1], qfl[2], qfl[3], qa + 128 * AT_ROWB);
#pragma unroll
            for (int nfp = 0; nfp < 4; nfp++) {
                uint32_t addrK = sb + (uint32_t)((16 * nfp + r8 + (g & 1) * 8) * AT_ROWB
                                                 + (16 * kf + (g >> 1) * 8) * 2);
                uint32_t r0, r1, r2, r3, u0, u1, u2, u3;
                LDSM_X4(r0, r1, r2, r3, addrK);
                LDSM_X4(u0, u1, u2, u3, addrK + AT_MATB);
                uint32_t bh0[2] = {r0, r2}, bh1[2] = {r1, r3};
                uint32_t bl0[2] = {u0, u2}, bl1[2] = {u1, u3};
                MMA_BF16(s[2 * nfp],     qfh, bh0);
                MMA_BF16(s[2 * nfp],     qfh, bl0);
                MMA_BF16(s[2 * nfp],     qfl, bh0);
                MMA_BF16(s[2 * nfp + 1], qfh, bh1);
                MMA_BF16(s[2 * nfp + 1], qfh, bl1);
                MMA_BF16(s[2 * nfp + 1], qfl, bh1);
            }
        }

        if (tc == NTe - 1) {
#pragma unroll
            for (int nf = 0; nf < 8; nf++) {
                int tcol = tc * 64 + nf * 8 + c2;
                if (tcol >= cnt)     { s[nf][0] = -100000.0f; s[nf][2] = -100000.0f; }
                if (tcol + 1 >= cnt) { s[nf][1] = -100000.0f; s[nf][3] = -100000.0f; }
            }
        }

        float mx0 = -1e30f, mx1 = -1e30f;
#pragma unroll
        for (int nf = 0; nf < 8; nf++) {
            mx0 = fmaxf(mx0, fmaxf(s[nf][0], s[nf][1]));
            mx1 = fmaxf(mx1, fmaxf(s[nf][2], s[nf][3]));
        }
        mx0 = fmaxf(mx0, __shfl_xor_sync(0xffffffffu, mx0, 1));
        mx0 = fmaxf(mx0, __shfl_xor_sync(0xffffffffu, mx0, 2));
        mx1 = fmaxf(mx1, __shfl_xor_sync(0xffffffffu, mx1, 1));
        mx1 = fmaxf(mx1, __shfl_xor_sync(0xffffffffu, mx1, 2));

        float mn0 = fmaxf(mr0, mx0), mn1 = fmaxf(mr1, mx1);
        float al0 = __expf(mr0 - mn0), al1 = __expf(mr1 - mn1);
        float sum0 = 0.0f, sum1 = 0.0f;
#pragma unroll
        for (int nf = 0; nf < 8; nf++) {
            s[nf][0] = __expf(s[nf][0] - mn0);
            s[nf][1] = __expf(s[nf][1] - mn0);
            s[nf][2] = __expf(s[nf][2] - mn1);
            s[nf][3] = __expf(s[nf][3] - mn1);
            sum0 += s[nf][0] + s[nf][1];
            sum1 += s[nf][2] + s[nf][3];
        }
        sum0 += __shfl_xor_sync(0xffffffffu, sum0, 1);
        sum0 += __shfl_xor_sync(0xffffffffu, sum0, 2);
        sum1 += __shfl_xor_sync(0xffffffffu, sum1, 1);
        sum1 += __shfl_xor_sync(0xffffffffu, sum1, 2);
        lr0 = lr0 * al0 + sum0;
        lr1 = lr1 * al1 + sum1;
        mr0 = mn0;
        mr1 = mn1;
#pragma unroll
        for (int nf = 0; nf < 8; nf++) {
            oacc[nf][0] *= al0;
            oacc[nf][1] *= al0;
            oacc[nf][2] *= al1;
            oacc[nf][3] *= al1;
        }

#pragma unroll
        for (int kf = 0; kf < 4; kf++) {
            uint32_t pah[4], pal[4];
#pragma unroll
            for (int q = 0; q < 2; q++) {
                const float* sp = s[2 * kf + q];
                __nv_bfloat162 h0 = __float22bfloat162_rn(make_float2(sp[0], sp[1]));
                float2 hf0 = __bfloat1622float2(h0);
                __nv_bfloat162 e0 = __float22bfloat162_rn(make_float2(sp[0] - hf0.x, sp[1] - hf0.y));
                __nv_bfloat162 h1 = __float22bfloat162_rn(make_float2(sp[2], sp[3]));
                float2 hf1 = __bfloat1622float2(h1);
                __nv_bfloat162 e1 = __float22bfloat162_rn(make_float2(sp[2] - hf1.x, sp[3] - hf1.y));
                pah[2 * q]     = *(uint32_t*)&h0;
                pah[2 * q + 1] = *(uint32_t*)&h1;
                pal[2 * q]     = *(uint32_t*)&e0;
                pal[2 * q + 1] = *(uint32_t*)&e1;
            }
#pragma unroll
            for (int nfp = 0; nfp < 4; nfp++) {
                uint32_t addrV = sb + 2 * AT_MATB
                               + (uint32_t)((16 * kf + r8 + (g & 1) * 8) * AT_ROWB
                                            + (16 * nfp + (g >> 1) * 8) * 2);
                uint32_t r0, r1, r2, r3, u0, u1, u2, u3;
                LDSM_X4_T(r0, r1, r2, r3, addrV);
                LDSM_X4_T(u0, u1, u2, u3, addrV + AT_MATB);
                uint32_t bvh0[2] = {r0, r1}, bvh1[2] = {r2, r3};
                uint32_t bvl0[2] = {u0, u1}, bvl1[2] = {u2, u3};
                MMA_BF16(oacc[2 * nfp],     pah, bvh0);
                MMA_BF16(oacc[2 * nfp],     pah, bvl0);
                MMA_BF16(oacc[2 * nfp],     pal, bvh0);
                MMA_BF16(oacc[2 * nfp + 1], pah, bvh1);
                MMA_BF16(oacc[2 * nfp + 1], pah, bvl1);
                MMA_BF16(oacc[2 * nfp + 1], pal, bvh1);
            }
        }

        if (tc + 1 < NTe) CP_ASYNC_WAIT0();
        __syncthreads();
    }

    float inv0 = 1.0f / lr0, inv1 = 1.0f / lr1;
    size_t row0 = (size_t)(b * S_LEN + s0 + w * 16 + (lane >> 2));
    size_t row1 = row0 + 8;
#pragma unroll
    for (int nf = 0; nf < 8; nf++) {
        int col = h * HEADD + nf * 8 + c2;
        float o0 = oacc[nf][0] * inv0, o1 = oacc[nf][1] * inv0;
        float o2 = oacc[nf][2] * inv1, o3 = oacc[nf][3] * inv1;
        __nv_bfloat162 h0 = __float22bfloat162_rn(make_float2(o0, o1));
        float2 hf0 = __bfloat1622float2(h0);
        __nv_bfloat162 e0 = __float22bfloat162_rn(make_float2(o0 - hf0.x, o1 - hf0.y));
        __nv_bfloat162 h1 = __float22bfloat162_rn(make_float2(o2, o3));
        float2 hf1 = __bfloat1622float2(h1);
        __nv_bfloat162 e1 = __float22bfloat162_rn(make_float2(o2 - hf1.x, o3 - hf1.y));
        *(__nv_bfloat162*)(oh + row0 * ADIM + col) = h0;
        *(__nv_bfloat162*)(ol + row0 * ADIM + col) = e0;
        *(__nv_bfloat162*)(oh + row1 * ADIM + col) = h1;
        *(__nv_bfloat162*)(ol + row1 * ADIM + col) = e1;
    }
}

// ---------------------------------------------------------------------------
// Launch
// ---------------------------------------------------------------------------
extern "C" void kernel_launch(void* const* d_in, const int* in_sizes, int n_in,
                              void* d_out, int out_size)
{
    const float* x  = (const float*)d_in[0];
    const float* y  = (const float*)d_in[1];
    const int*   mask = (const int*)d_in[2];
    const float* wq = (const float*)d_in[3];
    const float* bq = (const float*)d_in[4];
    const float* wk = (const float*)d_in[5];
    const float* bk = (const float*)d_in[6];
    const float* wv = (const float*)d_in[7];
    const float* bv = (const float*)d_in[8];
    const float* wo = (const float*)d_in[9];
    const float* bo = (const float*)d_in[10];
    float* out = (float*)d_out;

    __nv_bfloat16 *xh, *xl, *yh, *yl, *qhp, *qlp, *khp, *klp, *vhp, *vlp, *ohp, *olp;
    __nv_bfloat16 *wqh, *wql, *wkh, *wkl, *wvh, *wvl, *woh, *wol;
    int *destp, *cntp;
    cudaGetSymbolAddress((void**)&xh, g_xh);   cudaGetSymbolAddress((void**)&xl, g_xl);
    cudaGetSymbolAddress((void**)&yh, g_yh);   cudaGetSymbolAddress((void**)&yl, g_yl);
    cudaGetSymbolAddress((void**)&qhp, g_qh);  cudaGetSymbolAddress((void**)&qlp, g_ql);
    cudaGetSymbolAddress((void**)&khp, g_kh);  cudaGetSymbolAddress((void**)&klp, g_kl);
    cudaGetSymbolAddress((void**)&vhp, g_vh);  cudaGetSymbolAddress((void**)&vlp, g_vl);
    cudaGetSymbolAddress((void**)&ohp, g_oh);  cudaGetSymbolAddress((void**)&olp, g_ol);
    cudaGetSymbolAddress((void**)&wqh, g_wqh); cudaGetSymbolAddress((void**)&wql, g_wql);
    cudaGetSymbolAddress((void**)&wkh, g_wkh); cudaGetSymbolAddress((void**)&wkl, g_wkl);
    cudaGetSymbolAddress((void**)&wvh, g_wvh); cudaGetSymbolAddress((void**)&wvl, g_wvl);
    cudaGetSymbolAddress((void**)&woh, g_woh); cudaGetSymbolAddress((void**)&wol, g_wol);
    cudaGetSymbolAddress((void**)&destp, g_dest);
    cudaGetSymbolAddress((void**)&cntp, g_cnt);

    cudaFuncSetAttribute(gemm_qkv_kernel,
                         cudaFuncAttributeMaxDynamicSharedMemorySize, GEMM_DSMEM);
    cudaFuncSetAttribute(gemm_out_kernel,
                         cudaFuncAttributeMaxDynamicSharedMemorySize, GEMM_DSMEM);
    cudaFuncSetAttribute(flash_mma_kernel,
                         cudaFuncAttributeMaxDynamicSharedMemorySize, AT_DSMEM);

    const int n4_act = MROWS * HDIM / 4;

    // Mask compaction index
    build_index_kernel<<<BB, 256>>>(mask, destp, cntp);

    // Split activations (x and y fused)
    dim3 sg((n4_act + 255) / 256, 2);
    split2_kernel<<<sg, 256>>>((const float4*)x, (uint2*)xh, (uint2*)xl,
                               (const float4*)y, (uint2*)yh, (uint2*)yl, n4_act);

    // Transpose + split all 4 weights (fused)
    dim3 tg(32, 32, 4), tb(32, 8);
    transpose_split4_kernel<<<tg, tb>>>(wq, wqh, wql, wk, wkh, wkl,
                                        wv, wvh, wvl, wo, woh, wol);

    // Fused Q/K/V projections (z: 0=Q mode0, 1=K scatter, 2=V scatter)
    dim3 gq(G_N / 64, MROWS / 128, 3);   // (16, 64, 3)
    gemm_qkv_kernel<<<gq, 512, GEMM_DSMEM>>>(
        xh, xl, yh, yl, wqh, wql, wkh, wkl, wvh, wvl,
        bq, bk, bv, qhp, qlp, khp, klp, vhp, vlp, destp);

    // Flash attention over compacted K/V
    dim3 ga(S_LEN / 128, NHEAD, BB);
    flash_mma_kernel<<<ga, 256, AT_DSMEM>>>(qhp, qlp, khp, klp, vhp, vlp, cntp, ohp, olp);

    // Output projection -> fp32 out
    dim3 gg(G_N / 64, MROWS / 128);
    gemm_out_kernel<<<gg, 512, GEMM_DSMEM>>>(ohp, olp, woh, wol, bo, out);
}

// round 17
// speedup vs baseline: 1.2279x; 1.2279x over previous
#include <cuda_runtime.h>
#include <cuda_bf16.h>
#include <cstdint>

// Problem constants
#define BB     4
#define S_LEN  2048
#define T_LEN  2048
#define HDIM   1024
#define ADIM   1024
#define NHEAD  16
#define HEADD  64
#define MROWS  8192   // B*S == B*T

// ---------------------------------------------------------------------------
// Device scratch — zero-initialized; compacted tails stay 0 (deterministic)
// ---------------------------------------------------------------------------
__device__ __align__(16) __nv_bfloat16 g_xh[MROWS * HDIM];
__device__ __align__(16) __nv_bfloat16 g_xl[MROWS * HDIM];
__device__ __align__(16) __nv_bfloat16 g_ych[MROWS * HDIM];  // compacted y rows
__device__ __align__(16) __nv_bfloat16 g_ycl[MROWS * HDIM];
__device__ __align__(16) __nv_bfloat16 g_qh[MROWS * ADIM];
__device__ __align__(16) __nv_bfloat16 g_ql[MROWS * ADIM];
__device__ __align__(16) __nv_bfloat16 g_kh[MROWS * ADIM];
__device__ __align__(16) __nv_bfloat16 g_kl[MROWS * ADIM];
__device__ __align__(16) __nv_bfloat16 g_vh[MROWS * ADIM];
__device__ __align__(16) __nv_bfloat16 g_vl[MROWS * ADIM];
__device__ __align__(16) __nv_bfloat16 g_oh[MROWS * ADIM];
__device__ __align__(16) __nv_bfloat16 g_ol[MROWS * ADIM];
__device__ __align__(16) __nv_bfloat16 g_wqh[ADIM * HDIM];
__device__ __align__(16) __nv_bfloat16 g_wql[ADIM * HDIM];
__device__ __align__(16) __nv_bfloat16 g_wkh[ADIM * HDIM];
__device__ __align__(16) __nv_bfloat16 g_wkl[ADIM * HDIM];
__device__ __align__(16) __nv_bfloat16 g_wvh[ADIM * HDIM];
__device__ __align__(16) __nv_bfloat16 g_wvl[ADIM * HDIM];
__device__ __align__(16) __nv_bfloat16 g_woh[HDIM * ADIM];
__device__ __align__(16) __nv_bfloat16 g_wol[HDIM * ADIM];
__device__ int g_src[MROWS];    // inverse map: compacted j -> original t
__device__ int g_cnt[BB];       // unmasked count per batch

// ---------------------------------------------------------------------------
// PTX helpers (sm_80-era: legal on plain sm_103 target)
// ---------------------------------------------------------------------------
__device__ __forceinline__ uint32_t smem_u32(const void* p) {
    uint32_t a;
    asm("{ .reg .u64 t; cvta.to.shared.u64 t, %1; cvt.u32.u64 %0, t; }" : "=r"(a) : "l"(p));
    return a;
}

#define CP_ASYNC16(smem, gptr) \
    asm volatile("cp.async.cg.shared.global [%0], [%1], 16;" \
                 :: "r"((uint32_t)(smem)), "l"(gptr) : "memory")
#define CP_ASYNC_COMMIT() asm volatile("cp.async.commit_group;" ::: "memory")
#define CP_ASYNC_WAIT0()  asm volatile("cp.async.wait_group 0;" ::: "memory")
#define CP_ASYNC_WAIT1()  asm volatile("cp.async.wait_group 1;" ::: "memory")

#define LDSM_X4(r0, r1, r2, r3, a) \
    asm volatile("ldmatrix.sync.aligned.m8n8.x4.shared.b16 {%0,%1,%2,%3}, [%4];" \
                 : "=r"(r0), "=r"(r1), "=r"(r2), "=r"(r3) : "r"(a))
#define LDSM_X4_T(r0, r1, r2, r3, a) \
    asm volatile("ldmatrix.sync.aligned.m8n8.x4.trans.shared.b16 {%0,%1,%2,%3}, [%4];" \
                 : "=r"(r0), "=r"(r1), "=r"(r2), "=r"(r3) : "r"(a))
#define LDSM_X2(r0, r1, a) \
    asm volatile("ldmatrix.sync.aligned.m8n8.x2.shared.b16 {%0,%1}, [%2];" \
                 : "=r"(r0), "=r"(r1) : "r"(a))

#define MMA_BF16(d, a, b) \
    asm volatile("mma.sync.aligned.m16n8k16.row.col.f32.bf16.bf16.f32 " \
                 "{%0,%1,%2,%3}, {%4,%5,%6,%7}, {%8,%9}, {%0,%1,%2,%3};" \
                 : "+f"((d)[0]), "+f"((d)[1]), "+f"((d)[2]), "+f"((d)[3]) \
                 : "r"((a)[0]), "r"((a)[1]), "r"((a)[2]), "r"((a)[3]), \
                   "r"((b)[0]), "r"((b)[1]))

// ---------------------------------------------------------------------------
// Mask prefix scan: src[b*T+j] = original t of j-th unmasked; cnt[b]
// ---------------------------------------------------------------------------
__global__ __launch_bounds__(256) void build_index_kernel(
    const int* __restrict__ mask, int* __restrict__ src, int* __restrict__ cnts)
{
    __shared__ int warp_sums[8];
    const int b = blockIdx.x;
    const int* mb = mask + (size_t)b * T_LEN;
    const int tid = threadIdx.x;
    const int lane = tid & 31, wid = tid >> 5;

    int vals[8], local = 0;
#pragma unroll
    for (int i = 0; i < 8; i++) { vals[i] = (mb[tid * 8 + i] != 0) ? 1 : 0; local += vals[i]; }

    int pre = local;
#pragma unroll
    for (int o = 1; o < 32; o <<= 1) {
        int v = __shfl_up_sync(0xffffffffu, pre, o);
        if (lane >= o) pre += v;
    }
    if (lane == 31) warp_sums[wid] = pre;
    __syncthreads();
    int woff = 0;
#pragma unroll
    for (int i = 0; i < 8; i++) if (i < wid) woff += warp_sums[i];

    int excl = woff + pre - local;
#pragma unroll
    for (int i = 0; i < 8; i++) {
        if (vals[i]) src[b * T_LEN + excl] = tid * 8 + i;
        excl += vals[i];
    }
    if (tid == 255) cnts[b] = woff + pre;
}

// ---------------------------------------------------------------------------
// Split x -> bf16 hi/lo (full)
// ---------------------------------------------------------------------------
__global__ __launch_bounds__(256) void split_kernel(
    const float4* __restrict__ in, uint2* __restrict__ hi, uint2* __restrict__ lo, int n4)
{
    int i = blockIdx.x * 256 + threadIdx.x;
    if (i >= n4) return;
    float4 v = in[i];
    __nv_bfloat16 h0 = __float2bfloat16(v.x), h1 = __float2bfloat16(v.y);
    __nv_bfloat16 h2 = __float2bfloat16(v.z), h3 = __float2bfloat16(v.w);
    __nv_bfloat16 l0 = __float2bfloat16(v.x - __bfloat162float(h0));
    __nv_bfloat16 l1 = __float2bfloat16(v.y - __bfloat162float(h1));
    __nv_bfloat16 l2 = __float2bfloat16(v.z - __bfloat162float(h2));
    __nv_bfloat16 l3 = __float2bfloat16(v.w - __bfloat162float(h3));
    uint2 hw, lw;
    hw.x = (uint32_t)__bfloat16_as_ushort(h0) | ((uint32_t)__bfloat16_as_ushort(h1) << 16);
    hw.y = (uint32_t)__bfloat16_as_ushort(h2) | ((uint32_t)__bfloat16_as_ushort(h3) << 16);
    lw.x = (uint32_t)__bfloat16_as_ushort(l0) | ((uint32_t)__bfloat16_as_ushort(l1) << 16);
    lw.y = (uint32_t)__bfloat16_as_ushort(l2) | ((uint32_t)__bfloat16_as_ushort(l3) << 16);
    hi[i] = hw;
    lo[i] = lw;
}

// ---------------------------------------------------------------------------
// Gather + split y -> compacted yc hi/lo. One block per compacted row.
// ---------------------------------------------------------------------------
__global__ __launch_bounds__(256) void gather_split_kernel(
    const float4* __restrict__ y, const int* __restrict__ src,
    const int* __restrict__ cnts, uint2* __restrict__ ych, uint2* __restrict__ ycl)
{
    const int r = blockIdx.x;            // compacted row index 0..MROWS-1
    const int b = r >> 11, j = r & (T_LEN - 1);
    if (j >= cnts[b]) return;            // tail rows stay zero
    const int t = src[r];
    const float4* yr = y + (size_t)(b * T_LEN + t) * (HDIM / 4);
    const int i = threadIdx.x;           // 256 threads x 4 floats = 1024
    float4 v = yr[i];
    __nv_bfloat16 h0 = __float2bfloat16(v.x), h1 = __float2bfloat16(v.y);
    __nv_bfloat16 h2 = __float2bfloat16(v.z), h3 = __float2bfloat16(v.w);
    __nv_bfloat16 l0 = __float2bfloat16(v.x - __bfloat162float(h0));
    __nv_bfloat16 l1 = __float2bfloat16(v.y - __bfloat162float(h1));
    __nv_bfloat16 l2 = __float2bfloat16(v.z - __bfloat162float(h2));
    __nv_bfloat16 l3 = __float2bfloat16(v.w - __bfloat162float(h3));
    uint2 hw, lw;
    hw.x = (uint32_t)__bfloat16_as_ushort(h0) | ((uint32_t)__bfloat16_as_ushort(h1) << 16);
    hw.y = (uint32_t)__bfloat16_as_ushort(h2) | ((uint32_t)__bfloat16_as_ushort(h3) << 16);
    lw.x = (uint32_t)__bfloat16_as_ushort(l0) | ((uint32_t)__bfloat16_as_ushort(l1) << 16);
    lw.y = (uint32_t)__bfloat16_as_ushort(l2) | ((uint32_t)__bfloat16_as_ushort(l3) << 16);
    ych[(size_t)r * (HDIM / 4) + i] = hw;
    ycl[(size_t)r * (HDIM / 4) + i] = lw;
}

// ---------------------------------------------------------------------------
// Fused transpose+split of all 4 weights (blockIdx.z selects)
// ---------------------------------------------------------------------------
__global__ __launch_bounds__(256) void transpose_split4_kernel(
    const float* __restrict__ w0, __nv_bfloat16* __restrict__ t0h, __nv_bfloat16* __restrict__ t0l,
    const float* __restrict__ w1, __nv_bfloat16* __restrict__ t1h, __nv_bfloat16* __restrict__ t1l,
    const float* __restrict__ w2, __nv_bfloat16* __restrict__ t2h, __nv_bfloat16* __restrict__ t2l,
    const float* __restrict__ w3, __nv_bfloat16* __restrict__ t3h, __nv_bfloat16* __restrict__ t3l)
{
    __shared__ float t[32][33];
    const float* W;
    __nv_bfloat16 *th, *tl;
    switch (blockIdx.z) {
        case 0: W = w0; th = t0h; tl = t0l; break;
        case 1: W = w1; th = t1h; tl = t1l; break;
        case 2: W = w2; th = t2h; tl = t2l; break;
        default: W = w3; th = t3h; tl = t3l; break;
    }
    int tx = threadIdx.x, ty = threadIdx.y;
    int n0 = blockIdx.x * 32, k0 = blockIdx.y * 32;
#pragma unroll
    for (int i = 0; i < 32; i += 8)
        t[ty + i][tx] = W[(size_t)(k0 + ty + i) * 1024 + n0 + tx];
    __syncthreads();
#pragma unroll
    for (int i = 0; i < 32; i += 8) {
        float v = t[tx][ty + i];
        __nv_bfloat16 h = __float2bfloat16(v);
        __nv_bfloat16 l = __float2bfloat16(v - __bfloat162float(h));
        size_t o = (size_t)(n0 + ty + i) * 1024 + k0 + tx;
        th[o] = h;
        tl[o] = l;
    }
}

// ---------------------------------------------------------------------------
// GEMM common (R14-proven): CTA 128x64, 8 warps (4m x 2n), warp 32x32,
// 2 smem stages, 3 CTAs/SM (reg cap 85).
// ---------------------------------------------------------------------------
#define G_K     1024
#define G_N     1024
#define BKC     32
#define PAD_B   80
#define A_MATB  (128 * PAD_B)
#define B_MATB  (64 * PAD_B)
#define OFF_AH  0
#define OFF_AL  (A_MATB)
#define OFF_BH  (2 * A_MATB)
#define OFF_BL  (2 * A_MATB + B_MATB)
#define STAGE_B (2 * A_MATB + 2 * B_MATB)   // 30720
#define GEMM_DSMEM (2 * STAGE_B)            // 61440

__device__ __forceinline__ void gemm_load_stage(
    uint32_t sb, const __nv_bfloat16* __restrict__ Ah, const __nv_bfloat16* __restrict__ Al,
    const __nv_bfloat16* __restrict__ Bh, const __nv_bfloat16* __restrict__ Bl,
    int m0, int n0, int k0, int tid)
{
#pragma unroll
    for (int i = 0; i < 2; i++) {
        int idx = tid + i * 256;
        int r = idx >> 2, sg = idx & 3;
        uint32_t so = (uint32_t)(r * PAD_B + sg * 16);
        size_t ga = (size_t)(m0 + r) * G_K + k0 + sg * 8;
        CP_ASYNC16(sb + OFF_AH + so, Ah + ga);
        CP_ASYNC16(sb + OFF_AL + so, Al + ga);
    }
    {
        int r = tid >> 2, sg = tid & 3;
        uint32_t so = (uint32_t)(r * PAD_B + sg * 16);
        size_t gb = (size_t)(n0 + r) * G_K + k0 + sg * 8;
        CP_ASYNC16(sb + OFF_BH + so, Bh + gb);
        CP_ASYNC16(sb + OFF_BL + so, Bl + gb);
    }
}

__device__ __forceinline__ void gemm_mainloop(
    uint32_t sm0, const __nv_bfloat16* __restrict__ Ah, const __nv_bfloat16* __restrict__ Al,
    const __nv_bfloat16* __restrict__ Bh, const __nv_bfloat16* __restrict__ Bl,
    int m0, int n0, int tid, int wm, int wn, int lane, float acc[2][4][4])
{
    const int t4 = lane >> 3;
    const uint32_t a_lane_off = (uint32_t)(((lane & 7) + ((t4 & 1) << 3)) * PAD_B
                                           + ((t4 >> 1) << 3) * 2);
    const int li = lane & 15;
    const uint32_t b_lane_off = (uint32_t)((li & 7) * PAD_B + ((li >> 3) << 3) * 2);

    gemm_load_stage(sm0, Ah, Al, Bh, Bl, m0, n0, 0, tid);
    CP_ASYNC_COMMIT();

    const int NCH = G_K / BKC;
    for (int kc = 0; kc < NCH; kc++) {
        const uint32_t sb = sm0 + (kc & 1) * STAGE_B;
        if (kc + 1 < NCH) {
            gemm_load_stage(sm0 + ((kc + 1) & 1) * STAGE_B, Ah, Al, Bh, Bl,
                            m0, n0, (kc + 1) * BKC, tid);
            CP_ASYNC_COMMIT();
            CP_ASYNC_WAIT1();
        } else {
            CP_ASYNC_WAIT0();
        }
        __syncthreads();

#pragma unroll
        for (int ks = 0; ks < 2; ks++) {
            const uint32_t kb = (uint32_t)(ks * 16 * 2);
            uint32_t bh[4][2], bl[4][2];
#pragma unroll
            for (int nf = 0; nf < 4; nf++) {
                uint32_t base = (uint32_t)((wn * 32 + nf * 8) * PAD_B) + kb + b_lane_off;
                LDSM_X2(bh[nf][0], bh[nf][1], sb + OFF_BH + base);
                LDSM_X2(bl[nf][0], bl[nf][1], sb + OFF_BL + base);
            }
#pragma unroll
            for (int mf = 0; mf < 2; mf++) {
                uint32_t base = (uint32_t)((wm * 32 + mf * 16) * PAD_B) + kb + a_lane_off;
                uint32_t ah[4], al[4];
                LDSM_X4(ah[0], ah[1], ah[2], ah[3], sb + OFF_AH + base);
                LDSM_X4(al[0], al[1], al[2], al[3], sb + OFF_AL + base);
#pragma unroll
                for (int nf = 0; nf < 4; nf++) {
                    MMA_BF16(acc[mf][nf], ah, bh[nf]);
                    MMA_BF16(acc[mf][nf], ah, bl[nf]);
                    MMA_BF16(acc[mf][nf], al, bh[nf]);
                }
            }
        }
        __syncthreads();
    }
}

// Fused Q/K/V projections. z=0: Q from x (full). z=1,2: K/V from compacted yc
// with per-batch tile early-exit; outputs written directly (already compacted).
__global__ __launch_bounds__(256, 3) void gemm_qkv_kernel(
    const __nv_bfloat16* __restrict__ xh, const __nv_bfloat16* __restrict__ xl,
    const __nv_bfloat16* __restrict__ ych, const __nv_bfloat16* __restrict__ ycl,
    const __nv_bfloat16* __restrict__ wqh, const __nv_bfloat16* __restrict__ wql,
    const __nv_bfloat16* __restrict__ wkh, const __nv_bfloat16* __restrict__ wkl,
    const __nv_bfloat16* __restrict__ wvh, const __nv_bfloat16* __restrict__ wvl,
    const float* __restrict__ bq, const float* __restrict__ bk, const float* __restrict__ bv,
    __nv_bfloat16* __restrict__ qh, __nv_bfloat16* __restrict__ ql,
    __nv_bfloat16* __restrict__ kh, __nv_bfloat16* __restrict__ kl,
    __nv_bfloat16* __restrict__ vh, __nv_bfloat16* __restrict__ vl,
    const int* __restrict__ cnts)
{
    extern __shared__ __align__(16) char dsm[];
    const uint32_t sm0 = smem_u32(dsm);
    const int tid = threadIdx.x;
    const int wid = tid >> 5;
    const int lane = tid & 31;
    const int wm = wid >> 1;
    const int wn = wid & 1;
    const int m0 = blockIdx.y * 128;
    const int n0 = blockIdx.x * 64;
    const int z = blockIdx.z;

    // K/V: skip tiles entirely past the compacted row count of this batch.
    if (z != 0) {
        if ((m0 & (T_LEN - 1)) >= cnts[m0 >> 11]) return;
    }

    const __nv_bfloat16* Ah = (z == 0) ? xh : ych;
    const __nv_bfloat16* Al = (z == 0) ? xl : ycl;
    const __nv_bfloat16* Bh = (z == 0) ? wqh : ((z == 1) ? wkh : wvh);
    const __nv_bfloat16* Bl = (z == 0) ? wql : ((z == 1) ? wkl : wvl);
    const float* bias = (z == 0) ? bq : ((z == 1) ? bk : bv);
    __nv_bfloat16* Ch = (z == 0) ? qh : ((z == 1) ? kh : vh);
    __nv_bfloat16* Cl = (z == 0) ? ql : ((z == 1) ? kl : vl);
    const float scale = (z == 0) ? 0.125f : 1.0f;

    float acc[2][4][4];
#pragma unroll
    for (int i = 0; i < 2; i++)
#pragma unroll
        for (int j = 0; j < 4; j++)
#pragma unroll
            for (int c = 0; c < 4; c++) acc[i][j][c] = 0.0f;

    gemm_mainloop(sm0, Ah, Al, Bh, Bl, m0, n0, tid, wm, wn, lane, acc);

#pragma unroll
    for (int mf = 0; mf < 2; mf++) {
        int row0 = m0 + wm * 32 + mf * 16 + (lane >> 2);
        int row1 = row0 + 8;
#pragma unroll
        for (int nf = 0; nf < 4; nf++) {
            int col = n0 + wn * 32 + nf * 8 + ((lane & 3) << 1);
            float b0 = bias[col], b1 = bias[col + 1];
            float o0 = scale * (acc[mf][nf][0] + b0);
            float o1 = scale * (acc[mf][nf][1] + b1);
            float o2 = scale * (acc[mf][nf][2] + b0);
            float o3 = scale * (acc[mf][nf][3] + b1);
            __nv_bfloat162 h0 = __float22bfloat162_rn(make_float2(o0, o1));
            float2 hf0 = __bfloat1622float2(h0);
            __nv_bfloat162 l0 = __float22bfloat162_rn(make_float2(o0 - hf0.x, o1 - hf0.y));
            __nv_bfloat162 h1 = __float22bfloat162_rn(make_float2(o2, o3));
            float2 hf1 = __bfloat1622float2(h1);
            __nv_bfloat162 l1 = __float22bfloat162_rn(make_float2(o2 - hf1.x, o3 - hf1.y));
            *(__nv_bfloat162*)(Ch + (size_t)row0 * G_N + col) = h0;
            *(__nv_bfloat162*)(Cl + (size_t)row0 * G_N + col) = l0;
            *(__nv_bfloat162*)(Ch + (size_t)row1 * G_N + col) = h1;
            *(__nv_bfloat162*)(Cl + (size_t)row1 * G_N + col) = l1;
        }
    }
}

// Output projection: fp32 epilogue.
__global__ __launch_bounds__(256, 3) void gemm_out_kernel(
    const __nv_bfloat16* __restrict__ Ah, const __nv_bfloat16* __restrict__ Al,
    const __nv_bfloat16* __restrict__ Bh, const __nv_bfloat16* __restrict__ Bl,
    const float* __restrict__ bias, float* __restrict__ Cf)
{
    extern __shared__ __align__(16) char dsm[];
    const uint32_t sm0 = smem_u32(dsm);
    const int tid = threadIdx.x;
    const int wid = tid >> 5;
    const int lane = tid & 31;
    const int wm = wid >> 1;
    const int wn = wid & 1;
    const int m0 = blockIdx.y * 128;
    const int n0 = blockIdx.x * 64;

    float acc[2][4][4];
#pragma unroll
    for (int i = 0; i < 2; i++)
#pragma unroll
        for (int j = 0; j < 4; j++)
#pragma unroll
            for (int c = 0; c < 4; c++) acc[i][j][c] = 0.0f;

    gemm_mainloop(sm0, Ah, Al, Bh, Bl, m0, n0, tid, wm, wn, lane, acc);

#pragma unroll
    for (int mf = 0; mf < 2; mf++) {
        int row0 = m0 + wm * 32 + mf * 16 + (lane >> 2);
        int row1 = row0 + 8;
#pragma unroll
        for (int nf = 0; nf < 4; nf++) {
            int col = n0 + wn * 32 + nf * 8 + ((lane & 3) << 1);
            float b0 = bias[col], b1 = bias[col + 1];
            float2 v0 = make_float2(acc[mf][nf][0] + b0, acc[mf][nf][1] + b1);
            float2 v1 = make_float2(acc[mf][nf][2] + b0, acc[mf][nf][3] + b1);
            *(float2*)(Cf + (size_t)row0 * G_N + col) = v0;
            *(float2*)(Cf + (size_t)row1 * G_N + col) = v1;
        }
    }
}

// ---------------------------------------------------------------------------
// Tensorized flash attention v3: K/V pre-compacted (unchanged from R13 win).
// ---------------------------------------------------------------------------
#define AT_ROWB 144
#define AT_MATB (64 * AT_ROWB)
#define AT_STGB (4 * AT_MATB)
#define AT_QB   (2 * 128 * AT_ROWB)
#define AT_KV0  AT_QB
#define AT_DSMEM (AT_QB + 2 * AT_STGB)  // 110592

__device__ __forceinline__ void at_load_kv(
    uint32_t sb, const __nv_bfloat16* khb, const __nv_bfloat16* klb,
    const __nv_bfloat16* vhb, const __nv_bfloat16* vlb, int t0, int tid)
{
#pragma unroll
    for (int it = 0; it < 2; it++) {
        int id = tid + it * 256;
        int r = id >> 3, c = id & 7;
        uint32_t so = (uint32_t)(r * AT_ROWB + c * 16);
        size_t go = (size_t)(t0 + r) * ADIM + c * 8;
        CP_ASYNC16(sb + 0 * AT_MATB + so, khb + go);
        CP_ASYNC16(sb + 1 * AT_MATB + so, klb + go);
        CP_ASYNC16(sb + 2 * AT_MATB + so, vhb + go);
        CP_ASYNC16(sb + 3 * AT_MATB + so, vlb + go);
    }
}

__global__ __launch_bounds__(256, 2) void flash_mma_kernel(
    const __nv_bfloat16* __restrict__ qh, const __nv_bfloat16* __restrict__ ql,
    const __nv_bfloat16* __restrict__ kh, const __nv_bfloat16* __restrict__ kl,
    const __nv_bfloat16* __restrict__ vh, const __nv_bfloat16* __restrict__ vl,
    const int* __restrict__ cnts,
    __nv_bfloat16* __restrict__ oh, __nv_bfloat16* __restrict__ ol)
{
    extern __shared__ __align__(16) char dsm[];
    const uint32_t sm0 = smem_u32(dsm);
    const int tid = threadIdx.x;
    const int w = tid >> 5;
    const int lane = tid & 31;
    const int s0 = blockIdx.x * 128;
    const int h = blockIdx.y;
    const int b = blockIdx.z;

    const int cnt = cnts[b];
    const int NTe = (cnt + 63) >> 6;

    const __nv_bfloat16* qhb = qh + (size_t)(b * S_LEN + s0) * ADIM + h * HEADD;
    const __nv_bfloat16* qlb = ql + (size_t)(b * S_LEN + s0) * ADIM + h * HEADD;
    const __nv_bfloat16* khb = kh + (size_t)(b * T_LEN) * ADIM + h * HEADD;
    const __nv_bfloat16* klb = kl + (size_t)(b * T_LEN) * ADIM + h * HEADD;
    const __nv_bfloat16* vhb = vh + (size_t)(b * T_LEN) * ADIM + h * HEADD;
    const __nv_bfloat16* vlb = vl + (size_t)(b * T_LEN) * ADIM + h * HEADD;

#pragma unroll
    for (int it = 0; it < 4; it++) {
        int id = tid + it * 256;
        int r = id >> 3, c = id & 7;
        uint32_t so = (uint32_t)(r * AT_ROWB + c * 16);
        size_t go = (size_t)r * ADIM + c * 8;
        CP_ASYNC16(sm0 + so, qhb + go);
        CP_ASYNC16(sm0 + 128 * AT_ROWB + so, qlb + go);
    }
    at_load_kv(sm0 + AT_KV0, khb, klb, vhb, vlb, 0, tid);
    CP_ASYNC_COMMIT();

    const int r8 = lane & 7;
    const int g = lane >> 3;
    const uint32_t q_base = sm0 + (uint32_t)((w * 16 + r8 + (g & 1) * 8) * AT_ROWB
                                             + ((g >> 1) << 3) * 2);

    float oacc[8][4];
#pragma unroll
    for (int i = 0; i < 8; i++)
#pragma unroll
        for (int c = 0; c < 4; c++) oacc[i][c] = 0.0f;
    float mr0 = -1e30f, mr1 = -1e30f, lr0 = 0.0f, lr1 = 0.0f;

    const int c2 = (lane & 3) << 1;

    CP_ASYNC_WAIT0();
    __syncthreads();

    for (int tc = 0; tc < NTe; tc++) {
        const uint32_t sb = sm0 + AT_KV0 + (tc & 1) * AT_STGB;
        if (tc + 1 < NTe) {
            at_load_kv(sm0 + AT_KV0 + ((tc + 1) & 1) * AT_STGB, khb, klb, vhb, vlb,
                       (tc + 1) * 64, tid);
            CP_ASYNC_COMMIT();
        }

        float s[8][4];
#pragma unroll
        for (int i = 0; i < 8; i++)
#pragma unroll
            for (int c = 0; c < 4; c++) s[i][c] = 0.0f;

#pragma unroll
        for (int kf = 0; kf < 4; kf++) {
            uint32_t qa = q_base + (uint32_t)(16 * kf * 2);
            uint32_t qfh[4], qfl[4];
            LDSM_X4(qfh[0], qfh[1], qfh[2], qfh[3], qa);
            LDSM_X4(qfl[0], qfl[1], qfl[2], qfl[3], qa + 128 * AT_ROWB);
#pragma unroll
            for (int nfp = 0; nfp < 4; nfp++) {
                uint32_t addrK = sb + (uint32_t)((16 * nfp + r8 + (g & 1) * 8) * AT_ROWB
                                                 + (16 * kf + (g >> 1) * 8) * 2);
                uint32_t r0, r1, r2, r3, u0, u1, u2, u3;
                LDSM_X4(r0, r1, r2, r3, addrK);
                LDSM_X4(u0, u1, u2, u3, addrK + AT_MATB);
                uint32_t bh0[2] = {r0, r2}, bh1[2] = {r1, r3};
                uint32_t bl0[2] = {u0, u2}, bl1[2] = {u1, u3};
                MMA_BF16(s[2 * nfp],     qfh, bh0);
                MMA_BF16(s[2 * nfp],     qfh, bl0);
                MMA_BF16(s[2 * nfp],     qfl, bh0);
                MMA_BF16(s[2 * nfp + 1], qfh, bh1);
                MMA_BF16(s[2 * nfp + 1], qfh, bl1);
                MMA_BF16(s[2 * nfp + 1], qfl, bh1);
            }
        }

        if (tc == NTe - 1) {
#pragma unroll
            for (int nf = 0; nf < 8; nf++) {
                int tcol = tc * 64 + nf * 8 + c2;
                if (tcol >= cnt)     { s[nf][0] = -100000.0f; s[nf][2] = -100000.0f; }
                if (tcol + 1 >= cnt) { s[nf][1] = -100000.0f; s[nf][3] = -100000.0f; }
            }
        }

        float mx0 = -1e30f, mx1 = -1e30f;
#pragma unroll
        for (int nf = 0; nf < 8; nf++) {
            mx0 = fmaxf(mx0, fmaxf(s[nf][0], s[nf][1]));
            mx1 = fmaxf(mx1, fmaxf(s[nf][2], s[nf][3]));
        }
        mx0 = fmaxf(mx0, __shfl_xor_sync(0xffffffffu, mx0, 1));
        mx0 = fmaxf(mx0, __shfl_xor_sync(0xffffffffu, mx0, 2));
        mx1 = fmaxf(mx1, __shfl_xor_sync(0xffffffffu, mx1, 1));
        mx1 = fmaxf(mx1, __shfl_xor_sync(0xffffffffu, mx1, 2));

        float mn0 = fmaxf(mr0, mx0), mn1 = fmaxf(mr1, mx1);
        float al0 = __expf(mr0 - mn0), al1 = __expf(mr1 - mn1);
        float sum0 = 0.0f, sum1 = 0.0f;
#pragma unroll
        for (int nf = 0; nf < 8; nf++) {
            s[nf][0] = __expf(s[nf][0] - mn0);
            s[nf][1] = __expf(s[nf][1] - mn0);
            s[nf][2] = __expf(s[nf][2] - mn1);
            s[nf][3] = __expf(s[nf][3] - mn1);
            sum0 += s[nf][0] + s[nf][1];
            sum1 += s[nf][2] + s[nf][3];
        }
        sum0 += __shfl_xor_sync(0xffffffffu, sum0, 1);
        sum0 += __shfl_xor_sync(0xffffffffu, sum0, 2);
        sum1 += __shfl_xor_sync(0xffffffffu, sum1, 1);
        sum1 += __shfl_xor_sync(0xffffffffu, sum1, 2);
        lr0 = lr0 * al0 + sum0;
        lr1 = lr1 * al1 + sum1;
        mr0 = mn0;
        mr1 = mn1;
#pragma unroll
        for (int nf = 0; nf < 8; nf++) {
            oacc[nf][0] *= al0;
            oacc[nf][1] *= al0;
            oacc[nf][2] *= al1;
            oacc[nf][3] *= al1;
        }

#pragma unroll
        for (int kf = 0; kf < 4; kf++) {
            uint32_t pah[4], pal[4];
#pragma unroll
            for (int q = 0; q < 2; q++) {
                const float* sp = s[2 * kf + q];
                __nv_bfloat162 h0 = __float22bfloat162_rn(make_float2(sp[0], sp[1]));
                float2 hf0 = __bfloat1622float2(h0);
                __nv_bfloat162 e0 = __float22bfloat162_rn(make_float2(sp[0] - hf0.x, sp[1] - hf0.y));
                __nv_bfloat162 h1 = __float22bfloat162_rn(make_float2(sp[2], sp[3]));
                float2 hf1 = __bfloat1622float2(h1);
                __nv_bfloat162 e1 = __float22bfloat162_rn(make_float2(sp[2] - hf1.x, sp[3] - hf1.y));
                pah[2 * q]     = *(uint32_t*)&h0;
                pah[2 * q + 1] = *(uint32_t*)&h1;
                pal[2 * q]     = *(uint32_t*)&e0;
                pal[2 * q + 1] = *(uint32_t*)&e1;
            }
#pragma unroll
            for (int nfp = 0; nfp < 4; nfp++) {
                uint32_t addrV = sb + 2 * AT_MATB
                               + (uint32_t)((16 * kf + r8 + (g & 1) * 8) * AT_ROWB
                                            + (16 * nfp + (g >> 1) * 8) * 2);
                uint32_t r0, r1, r2, r3, u0, u1, u2, u3;
                LDSM_X4_T(r0, r1, r2, r3, addrV);
                LDSM_X4_T(u0, u1, u2, u3, addrV + AT_MATB);
                uint32_t bvh0[2] = {r0, r1}, bvh1[2] = {r2, r3};
                uint32_t bvl0[2] = {u0, u1}, bvl1[2] = {u2, u3};
                MMA_BF16(oacc[2 * nfp],     pah, bvh0);
                MMA_BF16(oacc[2 * nfp],     pah, bvl0);
                MMA_BF16(oacc[2 * nfp],     pal, bvh0);
                MMA_BF16(oacc[2 * nfp + 1], pah, bvh1);
                MMA_BF16(oacc[2 * nfp + 1], pah, bvl1);
                MMA_BF16(oacc[2 * nfp + 1], pal, bvh1);
            }
        }

        if (tc + 1 < NTe) CP_ASYNC_WAIT0();
        __syncthreads();
    }

    float inv0 = 1.0f / lr0, inv1 = 1.0f / lr1;
    size_t row0 = (size_t)(b * S_LEN + s0 + w * 16 + (lane >> 2));
    size_t row1 = row0 + 8;
#pragma unroll
    for (int nf = 0; nf < 8; nf++) {
        int col = h * HEADD + nf * 8 + c2;
        float o0 = oacc[nf][0] * inv0, o1 = oacc[nf][1] * inv0;
        float o2 = oacc[nf][2] * inv1, o3 = oacc[nf][3] * inv1;
        __nv_bfloat162 h0 = __float22bfloat162_rn(make_float2(o0, o1));
        float2 hf0 = __bfloat1622float2(h0);
        __nv_bfloat162 e0 = __float22bfloat162_rn(make_float2(o0 - hf0.x, o1 - hf0.y));
        __nv_bfloat162 h1 = __float22bfloat162_rn(make_float2(o2, o3));
        float2 hf1 = __bfloat1622float2(h1);
        __nv_bfloat162 e1 = __float22bfloat162_rn(make_float2(o2 - hf1.x, o3 - hf1.y));
        *(__nv_bfloat162*)(oh + row0 * ADIM + col) = h0;
        *(__nv_bfloat162*)(ol + row0 * ADIM + col) = e0;
        *(__nv_bfloat162*)(oh + row1 * ADIM + col) = h1;
        *(__nv_bfloat162*)(ol + row1 * ADIM + col) = e1;
    }
}

// ---------------------------------------------------------------------------
// Launch
// ---------------------------------------------------------------------------
extern "C" void kernel_launch(void* const* d_in, const int* in_sizes, int n_in,
                              void* d_out, int out_size)
{
    const float* x  = (const float*)d_in[0];
    const float* y  = (const float*)d_in[1];
    const int*   mask = (const int*)d_in[2];
    const float* wq = (const float*)d_in[3];
    const float* bq = (const float*)d_in[4];
    const float* wk = (const float*)d_in[5];
    const float* bk = (const float*)d_in[6];
    const float* wv = (const float*)d_in[7];
    const float* bv = (const float*)d_in[8];
    const float* wo = (const float*)d_in[9];
    const float* bo = (const float*)d_in[10];
    float* out = (float*)d_out;

    __nv_bfloat16 *xh, *xl, *ych, *ycl, *qhp, *qlp, *khp, *klp, *vhp, *vlp, *ohp, *olp;
    __nv_bfloat16 *wqh, *wql, *wkh, *wkl, *wvh, *wvl, *woh, *wol;
    int *srcp, *cntp;
    cudaGetSymbolAddress((void**)&xh, g_xh);    cudaGetSymbolAddress((void**)&xl, g_xl);
    cudaGetSymbolAddress((void**)&ych, g_ych);  cudaGetSymbolAddress((void**)&ycl, g_ycl);
    cudaGetSymbolAddress((void**)&qhp, g_qh);   cudaGetSymbolAddress((void**)&qlp, g_ql);
    cudaGetSymbolAddress((void**)&khp, g_kh);   cudaGetSymbolAddress((void**)&klp, g_kl);
    cudaGetSymbolAddress((void**)&vhp, g_vh);   cudaGetSymbolAddress((void**)&vlp, g_vl);
    cudaGetSymbolAddress((void**)&ohp, g_oh);   cudaGetSymbolAddress((void**)&olp, g_ol);
    cudaGetSymbolAddress((void**)&wqh, g_wqh);  cudaGetSymbolAddress((void**)&wql, g_wql);
    cudaGetSymbolAddress((void**)&wkh, g_wkh);  cudaGetSymbolAddress((void**)&wkl, g_wkl);
    cudaGetSymbolAddress((void**)&wvh, g_wvh);  cudaGetSymbolAddress((void**)&wvl, g_wvl);
    cudaGetSymbolAddress((void**)&woh, g_woh);  cudaGetSymbolAddress((void**)&wol, g_wol);
    cudaGetSymbolAddress((void**)&srcp, g_src);
    cudaGetSymbolAddress((void**)&cntp, g_cnt);

    cudaFuncSetAttribute(gemm_qkv_kernel,
                         cudaFuncAttributeMaxDynamicSharedMemorySize, GEMM_DSMEM);
    cudaFuncSetAttribute(gemm_out_kernel,
                         cudaFuncAttributeMaxDynamicSharedMemorySize, GEMM_DSMEM);
    cudaFuncSetAttribute(flash_mma_kernel,
                         cudaFuncAttributeMaxDynamicSharedMemorySize, AT_DSMEM);

    const int n4_act = MROWS * HDIM / 4;

    // Mask compaction index (src = inverse map)
    build_index_kernel<<<BB, 256>>>(mask, srcp, cntp);

    // Split x (full); gather+split y into compacted yc
    split_kernel<<<(n4_act + 255) / 256, 256>>>((const float4*)x, (uint2*)xh, (uint2*)xl, n4_act);
    gather_split_kernel<<<MROWS, 256>>>((const float4*)y, srcp, cntp, (uint2*)ych, (uint2*)ycl);

    // Transpose + split all 4 weights (fused)
    dim3 tg(32, 32, 4), tb(32, 8);
    transpose_split4_kernel<<<tg, tb>>>(wq, wqh, wql, wk, wkh, wkl,
                                        wv, wvh, wvl, wo, woh, wol);

    // Fused Q/K/V projections (z: 0=Q full, 1=K compacted, 2=V compacted)
    dim3 gq(G_N / 64, MROWS / 128, 3);   // (16, 64, 3)
    gemm_qkv_kernel<<<gq, 256, GEMM_DSMEM>>>(
        xh, xl, ych, ycl, wqh, wql, wkh, wkl, wvh, wvl,
        bq, bk, bv, qhp, qlp, khp, klp, vhp, vlp, cntp);

    // Flash attention over compacted K/V
    dim3 ga(S_LEN / 128, NHEAD, BB);
    flash_mma_kernel<<<ga, 256, AT_DSMEM>>>(qhp, qlp, khp, klp, vhp, vlp, cntp, ohp, olp);

    // Output projection -> fp32 out
    dim3 gg(G_N / 64, MROWS / 128);
    gemm_out_kernel<<<gg, 256, GEMM_DSMEM>>>(ohp, olp, woh, wol, bo, out);
}